// round 16
// baseline (speedup 1.0000x reference)
#include <cuda_runtime.h>

#define NNODES 50000
#define D      128
#define G      64
#define KT     32
#define RB     64

// ---------------- scratch (device globals: allocation-free) ----------------
__device__ float g_h[NNODES * D];     // GEMM output (gather source)
__device__ float g_agg[NNODES * D];   // aggregation buffer (scatter target)
__device__ float g_deg[NNODES];
__device__ float g_dinv[NNODES];
__device__ float g_pool[2][G * D];
__device__ float g_cnt[2][G];

// ---------------- small utility kernels ----------------
__global__ void zero_deg_kernel(int n) {
    int i = blockIdx.x * blockDim.x + threadIdx.x;
    if (i < n) g_deg[i] = 0.f;
}

__global__ void zero_pool_kernel() {
    int i = blockIdx.x * blockDim.x + threadIdx.x;
    if (i < 2 * G * D) ((float*)g_pool)[i] = 0.f;
    if (i < 2 * G)     ((float*)g_cnt)[i]  = 0.f;
}

__global__ void deg_kernel(const int* __restrict__ dst, int E) {
    int i = blockIdx.x * blockDim.x + threadIdx.x;
    if (i < E) atomicAdd(&g_deg[dst[i]], 1.f);
}

__global__ void dinv_kernel(int n) {
    int i = blockIdx.x * blockDim.x + threadIdx.x;
    if (i < n) g_dinv[i] = rsqrtf(g_deg[i] + 1.f);   // deg incl. self-loop
}

// ---------------- GEMM: h = act(X) @ W ; epilogue writes h and agg=h*dinv^2+b
// Block: 256 threads, tile 64 rows x 128 cols. Each thread: 8 rows x 4 cols.
__global__ void __launch_bounds__(256) gemm_kernel(
    const float* __restrict__ Xin, const float* __restrict__ W,
    const float* __restrict__ bias, int nrows, int leaky_in)
{
    const float* X = Xin ? Xin : (const float*)g_agg;

    __shared__ float Ws[KT][D];        // 16 KB
    __shared__ float Xs[RB][KT + 4];   // 9 KB, row stride 36 floats (16B aligned)

    const int tid = threadIdx.x;
    const int tx  = tid & 31;          // col group: cols [4*tx, 4*tx+4)
    const int ty  = tid >> 5;          // row group: rows ty + r*8
    const int row0 = blockIdx.x * RB;

    float4 acc[8];
#pragma unroll
    for (int r = 0; r < 8; r++) acc[r] = make_float4(0.f, 0.f, 0.f, 0.f);

    for (int kt = 0; kt < D / KT; kt++) {
        // load W tile [KT][D] (coalesced)
#pragma unroll
        for (int i = tid; i < KT * D; i += 256) {
            int k = i >> 7, j = i & (D - 1);
            Ws[k][j] = W[(kt * KT + k) * D + j];
        }
        // load X tile [RB][KT] (coalesced, fused activation)
#pragma unroll
        for (int i = tid; i < RB * KT; i += 256) {
            int r = i >> 5, k = i & 31;
            int row = row0 + r;
            float v = (row < nrows) ? X[(size_t)row * D + kt * KT + k] : 0.f;
            if (leaky_in) v = v > 0.f ? v : 0.01f * v;
            Xs[r][k] = v;
        }
        __syncthreads();

#pragma unroll
        for (int k4 = 0; k4 < KT / 4; k4++) {
            float4 xv[8];
#pragma unroll
            for (int r = 0; r < 8; r++)
                xv[r] = *(const float4*)&Xs[ty + r * 8][k4 * 4];   // warp-uniform broadcast
#pragma unroll
            for (int kk = 0; kk < 4; kk++) {
                float4 w4 = *(const float4*)&Ws[k4 * 4 + kk][tx * 4];
#pragma unroll
                for (int r = 0; r < 8; r++) {
                    float xk = (kk == 0) ? xv[r].x : (kk == 1) ? xv[r].y
                              : (kk == 2) ? xv[r].z : xv[r].w;
                    acc[r].x = fmaf(xk, w4.x, acc[r].x);
                    acc[r].y = fmaf(xk, w4.y, acc[r].y);
                    acc[r].z = fmaf(xk, w4.z, acc[r].z);
                    acc[r].w = fmaf(xk, w4.w, acc[r].w);
                }
            }
        }
        __syncthreads();
    }

    // epilogue: g_h = h ; g_agg = h * dinv^2 + bias  (self-loop + bias pre-init)
    float4 b4 = *(const float4*)&bias[tx * 4];
#pragma unroll
    for (int r = 0; r < 8; r++) {
        int row = row0 + ty + r * 8;
        if (row < nrows) {
            float di   = g_dinv[row];
            float self = di * di;
            size_t o = (size_t)row * D + tx * 4;
            *(float4*)&g_h[o] = acc[r];
            float4 a;
            a.x = fmaf(acc[r].x, self, b4.x);
            a.y = fmaf(acc[r].y, self, b4.y);
            a.z = fmaf(acc[r].z, self, b4.z);
            a.w = fmaf(acc[r].w, self, b4.w);
            *(float4*)&g_agg[o] = a;
        }
    }
}

// ---------------- edge scatter: agg[dst] += h[src] * dinv[src]*dinv[dst]
// One warp per edge: 32 lanes x float4 = 128 floats, vector RED atomics.
__global__ void scatter_kernel(const int* __restrict__ src,
                               const int* __restrict__ dst, int E)
{
    int w = (blockIdx.x * blockDim.x + threadIdx.x) >> 5;
    int lane = threadIdx.x & 31;
    if (w >= E) return;
    int s = __ldg(&src[w]);
    int d = __ldg(&dst[w]);
    float norm = g_dinv[s] * g_dinv[d];
    float4 v = *(const float4*)&g_h[(size_t)s * D + lane * 4];
    float4 o = make_float4(v.x * norm, v.y * norm, v.z * norm, v.w * norm);
    atomicAdd((float4*)&g_agg[(size_t)d * D + lane * 4], o);   // -> RED.E.ADD.128
}

// ---------------- mean-pool numerators via sorted-batch segmented sums ----
// Block: 128 threads (one per col), chunk of 32 consecutive nodes.
__global__ void pool_kernel(const int* __restrict__ batch, int br, int n)
{
    int j  = threadIdx.x;
    int n0 = blockIdx.x * 32;
    int cn = min(32, n - n0);
    __shared__ int sb[32];
    if (j < 32) sb[j] = (j < cn) ? batch[n0 + j] : -1;
    __syncthreads();

    float* pool = g_pool[br];
    float* cnt  = g_cnt[br];
    int   cur = sb[0];
    float run = 0.f;
    int   len = 0;
    for (int t = 0; t < cn; t++) {
        int g = sb[t];
        float v = g_agg[(size_t)(n0 + t) * D + j];
        v = v > 0.f ? v : 0.01f * v;                 // fused leaky-ReLU
        if (g != cur) {
            atomicAdd(&pool[cur * D + j], run);
            if (j == 0) atomicAdd(&cnt[cur], (float)len);
            run = 0.f; len = 0; cur = g;
        }
        run += v; len++;
    }
    atomicAdd(&pool[cur * D + j], run);
    if (j == 0) atomicAdd(&cnt[cur], (float)len);
}

// ---------------- final MLP: out = relu(concat/cnt @ lin1 + b1) @ lin2 + b2
__global__ void final_kernel(const float* __restrict__ lin1W,
                             const float* __restrict__ lin1b,
                             const float* __restrict__ lin2W,
                             const float* __restrict__ lin2b,
                             float* __restrict__ out)
{
    int g = blockIdx.x, j = threadIdx.x;   // 64 blocks x 128 threads
    __shared__ float c[2 * D];
    __shared__ float red[D];
    c[j]     = g_pool[0][g * D + j] / fmaxf(g_cnt[0][g], 1.f);
    c[D + j] = g_pool[1][g * D + j] / fmaxf(g_cnt[1][g], 1.f);
    __syncthreads();

    float h = lin1b[j];
#pragma unroll 8
    for (int k = 0; k < 2 * D; k++) h = fmaf(c[k], lin1W[k * D + j], h);
    h = fmaxf(h, 0.f);

    red[j] = h * lin2W[j];
    __syncthreads();
    for (int s = 64; s > 0; s >>= 1) {
        if (j < s) red[j] += red[j + s];
        __syncthreads();
    }
    if (j == 0) out[g] = red[0] + lin2b[0];
}

// ---------------- host-side branch driver ----------------
static void run_branch(const float* x, const int* ei, const int* batch,
                       const float* W0, const float* b0,
                       const float* W1, const float* b1,
                       int br, int n, int E)
{
    const int* src = ei;
    const int* dst = ei + E;
    int nb = (n + 255) / 256;
    zero_deg_kernel<<<nb, 256>>>(n);
    deg_kernel<<<(E + 255) / 256, 256>>>(dst, E);
    dinv_kernel<<<nb, 256>>>(n);

    int gblocks = (n + RB - 1) / RB;
    long sblocks = ((long)E * 32 + 255) / 256;

    gemm_kernel<<<gblocks, 256>>>(x, W0, b0, n, 0);           // layer 1
    scatter_kernel<<<(int)sblocks, 256>>>(src, dst, E);
    gemm_kernel<<<gblocks, 256>>>(nullptr, W1, b1, n, 1);     // layer 2 (leaky in)
    scatter_kernel<<<(int)sblocks, 256>>>(src, dst, E);
    pool_kernel<<<(n + 31) / 32, 128>>>(batch, br, n);
}

extern "C" void kernel_launch(void* const* d_in, const int* in_sizes, int n_in,
                              void* d_out, int out_size)
{
    const float* x1     = (const float*)d_in[0];
    const int*   ei1    = (const int*)  d_in[1];
    const int*   batch1 = (const int*)  d_in[2];
    const float* x2     = (const float*)d_in[3];
    const int*   ei2    = (const int*)  d_in[4];
    const int*   batch2 = (const int*)  d_in[5];
    const float* W1_0 = (const float*)d_in[6];
    const float* b1_0 = (const float*)d_in[7];
    const float* W1_1 = (const float*)d_in[8];
    const float* b1_1 = (const float*)d_in[9];
    const float* W2_0 = (const float*)d_in[10];
    const float* b2_0 = (const float*)d_in[11];
    const float* W2_1 = (const float*)d_in[12];
    const float* b2_1 = (const float*)d_in[13];
    const float* lin1W = (const float*)d_in[14];
    const float* lin1b = (const float*)d_in[15];
    const float* lin2W = (const float*)d_in[16];
    const float* lin2b = (const float*)d_in[17];
    float* out = (float*)d_out;

    int n = in_sizes[0] / D;   // 50000
    int E = in_sizes[1] / 2;   // 800000

    zero_pool_kernel<<<(2 * G * D + 255) / 256, 256>>>();
    run_branch(x1, ei1, batch1, W1_0, b1_0, W1_1, b1_1, 0, n, E);
    run_branch(x2, ei2, batch2, W2_0, b2_0, W2_1, b2_1, 1, n, E);
    final_kernel<<<G, D>>>(lin1W, lin1b, lin2W, lin2b, out);
}